// round 16
// baseline (speedup 1.0000x reference)
#include <cuda_runtime.h>
#include <cuda_bf16.h>
#include <cstdint>
#include <math.h>

// Problem dims (fixed by the dataset)
#define N_TOK 8192
#define D_IN  1024
#define D_QK  128
#define D_V   1024
#define D_W1  1280
#define CAP   1024
#define NSM   148
#define ALPHA 11.313708498984760f   // sqrt(128)
#define THR_MARGIN 30               // int8 score units (x2 = 60 logit units)
#define QSCALE 16.0f                // q,k int8 quant scale (1/16 step)
#define SCONV  0.0220970869120796f  // ALPHA/(256*2): int32 acc -> int8 score units

// ---------------- scratch (static device globals; no allocs) ----------------
static __device__ __align__(16) __nv_bfloat16 g_xh [(size_t)N_TOK * D_IN];
static __device__ __align__(16) __nv_bfloat16 g_xl [(size_t)N_TOK * D_IN];
static __device__ __align__(16) __nv_bfloat16 g_W1h[(size_t)D_W1 * D_IN];
static __device__ __align__(16) __nv_bfloat16 g_W1l[(size_t)D_W1 * D_IN];
static __device__ __align__(16) __nv_bfloat16 g_Wlh[(size_t)D_V * D_IN];
static __device__ __align__(16) __nv_bfloat16 g_Wll[(size_t)D_V * D_IN];
static __device__ __align__(16) signed char   g_qki[(size_t)N_TOK * 256];  // int8 q|k (x16)
static __device__ __align__(16) float         g_qk [(size_t)N_TOK * 256];  // fp32 q|k
static __device__ __align__(16) __nv_bfloat16 g_hh [(size_t)N_TOK * D_IN];
static __device__ __align__(16) __nv_bfloat16 g_hl [(size_t)N_TOK * D_IN];
static __device__ float  g_v  [(size_t)N_TOK * D_V];
static __device__ __align__(16) signed char   g_Si[(size_t)N_TOK * N_TOK]; // int8 scores
static __device__ int    g_mi [N_TOK];
static __device__ int    g_cnt[N_TOK];
static __device__ float2 g_cand[(size_t)N_TOK * CAP];
static __device__ float  g_sa [(size_t)N_TOK * D_V];
static __device__ float  g_tmp[(size_t)N_TOK * D_V];

// ---------------- helpers ----------------
__device__ __forceinline__ uint32_t smem_u32(const void* p) {
    uint32_t a;
    asm("{ .reg .u64 t; cvta.to.shared.u64 t, %1; cvt.u32.u64 %0, t; }" : "=r"(a) : "l"(p));
    return a;
}
__device__ __forceinline__ void split_bf16(float v, __nv_bfloat16& h, __nv_bfloat16& l) {
    h = __float2bfloat16(v);
    l = __float2bfloat16(v - __bfloat162float(h));
}
__device__ __forceinline__ signed char quant_i8(float v) {
    int u = __float2int_rn(v);
    return (signed char)min(127, max(-127, u));
}

#define LDSM_X4(r, addr)                                                        \
    asm volatile("ldmatrix.sync.aligned.m8n8.x4.shared.b16 {%0,%1,%2,%3}, [%4];" \
        : "=r"((r)[0]), "=r"((r)[1]), "=r"((r)[2]), "=r"((r)[3]) : "r"(addr))

#define MMA_BF16(c, a, b)                                                       \
    asm volatile("mma.sync.aligned.m16n8k16.row.col.f32.bf16.bf16.f32 "         \
        "{%0,%1,%2,%3}, {%4,%5,%6,%7}, {%8,%9}, {%0,%1,%2,%3};"                 \
        : "+f"((c)[0]), "+f"((c)[1]), "+f"((c)[2]), "+f"((c)[3])                \
        : "r"((a)[0]), "r"((a)[1]), "r"((a)[2]), "r"((a)[3]),                   \
          "r"((b)[0]), "r"((b)[1]))

#define MMA_S8(c, a, b0, b1)                                                    \
    asm volatile("mma.sync.aligned.m16n8k32.row.col.s32.s8.s8.s32 "             \
        "{%0,%1,%2,%3}, {%4,%5,%6,%7}, {%8,%9}, {%0,%1,%2,%3};"                 \
        : "+r"((c)[0]), "+r"((c)[1]), "+r"((c)[2]), "+r"((c)[3])                \
        : "r"((a)[0]), "r"((a)[1]), "r"((a)[2]), "r"((a)[3]),                   \
          "r"(b0), "r"(b1))

#define LDS32(r, addr) \
    asm volatile("ld.shared.b32 %0, [%1];" : "=r"(r) : "r"(addr))

#define CP_ASYNC16(dst, src) \
    asm volatile("cp.async.cg.shared.global [%0], [%1], 16;" :: "r"(dst), "l"(src))
#define CP_COMMIT()  asm volatile("cp.async.commit_group;")
#define CP_WAIT(n)   asm volatile("cp.async.wait_group %0;" :: "n"(n))

// ---------------- combined prep: weight/x bf16 hi-lo split + init -----------
__global__ void prep_all(const float* __restrict__ x,
                         const float* __restrict__ Wq, const float* __restrict__ Wk,
                         const float* __restrict__ Wv, const float* __restrict__ Wl)
{
    const int stride = gridDim.x * blockDim.x;
    int g = blockIdx.x * blockDim.x + threadIdx.x;
    for (int i = g; i < D_W1 * D_IN; i += stride) {
        int r = i >> 10, c = i & 1023;
        float v;
        if (r < 128)      v = Wq[r * D_IN + c];
        else if (r < 256) v = Wk[(r - 128) * D_IN + c];
        else              v = Wv[(r - 256) * D_IN + c];
        split_bf16(v, g_W1h[i], g_W1l[i]);
    }
    for (int i = g; i < D_V * D_IN; i += stride)
        split_bf16(Wl[i], g_Wlh[i], g_Wll[i]);
    for (int i = g; i < N_TOK * D_IN; i += stride)
        split_bf16(x[i], g_xh[i], g_xl[i]);
    for (int i = g; i < N_TOK; i += stride)
        g_mi[i] = -(1 << 30);
}

// ---------------- bf16x3 tensor-core GEMM (PERSISTENT, 2 CTAs/SM) -----------
// MODE 0: qkv = x @ W1^T -> q,k fp32+int8 ; v fp32.  MODE 2: tmp = h @ Wl^T.
#define TILE_B 16384

template<int MODE>
__global__ __launch_bounds__(128, 2)
void gemm_mma()
{
    constexpr int CTA_M  = 64;
    constexpr int A_TILE = CTA_M * 128;
    constexpr int OFF_AH = 0;
    constexpr int OFF_AL = A_TILE;
    constexpr int OFF_BH = 2 * A_TILE;
    constexpr int OFF_BL = OFF_BH + TILE_B;
    constexpr int STAGE  = 2 * A_TILE + 2 * TILE_B;   // 48 KB

    extern __shared__ char smem[];
    const uint32_t sb  = smem_u32(smem);
    const int tid  = threadIdx.x;
    const int wid  = tid >> 5;
    const int lane = tid & 31;

    const __nv_bfloat16 *Ah, *Al, *Bh, *Bl;
    constexpr int lda = 1024;
    constexpr int K   = 1024;
    constexpr int ntn = (MODE == 0) ? 10 : 8;
    if constexpr (MODE == 0) { Ah = g_xh; Al = g_xl; Bh = g_W1h; Bl = g_W1l; }
    else                     { Ah = g_hh; Al = g_hl; Bh = g_Wlh; Bl = g_Wll; }

    constexpr int nch  = K / 64;
    constexpr int ntot = ntn * (N_TOK / CTA_M);

    auto load_stage = [&](int st, int t, int k0) {
        const int tm0 = (t / ntn) * CTA_M;
        const int tn0 = (t % ntn) * 128;
        const __nv_bfloat16* bsA[2] = { Ah + (size_t)tm0 * lda,
                                        Al + (size_t)tm0 * lda };
        const __nv_bfloat16* bsB[2] = { Bh + (size_t)tn0 * lda,
                                        Bl + (size_t)tn0 * lda };
#pragma unroll
        for (int it = 0; it < 24; it++) {
            int idx = tid + it * 128;
            const __nv_bfloat16* src;
            uint32_t dst;
            if (idx < 1024) {
                int half = idx >> 9;
                int r    = (idx >> 3) & 63;
                int g    = idx & 7;
                src = bsA[half] + (size_t)r * lda + k0 + g * 8;
                uint32_t off = (uint32_t)(r * 128 + g * 16);
                off ^= (off >> 3) & 0x70;
                dst = (half ? OFF_AL : OFF_AH) + off;
            } else {
                int idx2 = idx - 1024;
                int half = idx2 >> 10;
                int r    = (idx2 >> 3) & 127;
                int g    = idx2 & 7;
                src = bsB[half] + (size_t)r * lda + k0 + g * 8;
                uint32_t off = (uint32_t)(r * 128 + g * 16);
                off ^= (off >> 3) & 0x70;
                dst = (half ? OFF_BL : OFF_BH) + off;
            }
            CP_ASYNC16(sb + st * STAGE + dst, src);
        }
        CP_COMMIT();
    };

    const int wm = (wid & 1) * 32;
    const int wn = (wid >> 1) * 64;

    float acc[2][8][4];

    auto load_frags = [&](uint32_t base, int k16,
                          uint32_t (*ah)[4], uint32_t (*al)[4],
                          uint32_t (*bh)[4], uint32_t (*bl)[4]) {
#pragma unroll
        for (int mi = 0; mi < 2; mi++) {
            int row = wm + mi * 16 + (lane & 15);
            int c16 = k16 * 2 + (lane >> 4);
            uint32_t off = (uint32_t)(row * 128 + c16 * 16);
            off ^= (off >> 3) & 0x70;
            LDSM_X4(ah[mi], base + OFF_AH + off);
            LDSM_X4(al[mi], base + OFF_AL + off);
        }
#pragma unroll
        for (int nj = 0; nj < 4; nj++) {
            int row = wn + nj * 16 + (lane & 7) + ((lane >> 4) << 3);
            int c16 = k16 * 2 + ((lane >> 3) & 1);
            uint32_t off = (uint32_t)(row * 128 + c16 * 16);
            off ^= (off >> 3) & 0x70;
            LDSM_X4(bh[nj], base + OFF_BH + off);
            LDSM_X4(bl[nj], base + OFF_BL + off);
        }
    };

    auto compute_stage = [&](int st) {
        const uint32_t base = sb + st * STAGE;
        uint32_t ah[2][2][4], al[2][2][4], bh[2][4][4], bl[2][4][4];
        load_frags(base, 0, ah[0], al[0], bh[0], bl[0]);
#pragma unroll
        for (int k16 = 0; k16 < 4; k16++) {
            const int cur = k16 & 1;
#pragma unroll
            for (int mi = 0; mi < 2; mi++)
#pragma unroll
                for (int nj = 0; nj < 4; nj++) {
                    MMA_BF16(acc[mi][nj * 2],     ah[cur][mi], (bh[cur][nj] + 0));
                    MMA_BF16(acc[mi][nj * 2 + 1], ah[cur][mi], (bh[cur][nj] + 2));
                }
            if (k16 < 3)
                load_frags(base, k16 + 1, ah[cur ^ 1], al[cur ^ 1],
                           bh[cur ^ 1], bl[cur ^ 1]);
#pragma unroll
            for (int mi = 0; mi < 2; mi++)
#pragma unroll
                for (int nj = 0; nj < 4; nj++) {
                    MMA_BF16(acc[mi][nj * 2],     ah[cur][mi], (bl[cur][nj] + 0));
                    MMA_BF16(acc[mi][nj * 2 + 1], ah[cur][mi], (bl[cur][nj] + 2));
                }
#pragma unroll
            for (int mi = 0; mi < 2; mi++)
#pragma unroll
                for (int nj = 0; nj < 4; nj++) {
                    MMA_BF16(acc[mi][nj * 2],     al[cur][mi], (bh[cur][nj] + 0));
                    MMA_BF16(acc[mi][nj * 2 + 1], al[cur][mi], (bh[cur][nj] + 2));
                }
        }
    };

    const int qr = lane >> 2;
    const int qc = (lane & 3) * 2;

    auto epilogue = [&](int t) {
        const int m0 = (t / ntn) * CTA_M;
        const int n0 = (t % ntn) * 128;
        if constexpr (MODE == 0) {
#pragma unroll
            for (int mi = 0; mi < 2; mi++) {
                const int r0 = m0 + wm + mi * 16 + qr;
#pragma unroll
                for (int ni = 0; ni < 8; ni++) {
                    const int col = n0 + wn + ni * 8 + qc;
                    if (col < 256) {
#pragma unroll
                        for (int half = 0; half < 2; half++) {
                            const int rr = r0 + half * 8;
                            float v0 = acc[mi][ni][half * 2 + 0];
                            float v1 = acc[mi][ni][half * 2 + 1];
                            *(float2*)(g_qk + (size_t)rr * 256 + col) = make_float2(v0, v1);
                            char2 qi = { quant_i8(v0 * QSCALE), quant_i8(v1 * QSCALE) };
                            *(char2*)(g_qki + (size_t)rr * 256 + col) = qi;
                        }
                    } else {
                        const int vc = col - 256;
                        *(float2*)(g_v + (size_t)r0 * D_V + vc) =
                            make_float2(acc[mi][ni][0], acc[mi][ni][1]);
                        *(float2*)(g_v + (size_t)(r0 + 8) * D_V + vc) =
                            make_float2(acc[mi][ni][2], acc[mi][ni][3]);
                    }
                }
            }
        } else {
#pragma unroll
            for (int mi = 0; mi < 2; mi++) {
                const int r0 = m0 + wm + mi * 16 + qr;
#pragma unroll
                for (int ni = 0; ni < 8; ni++) {
                    const int col = n0 + wn + ni * 8 + qc;
                    *(float2*)(g_tmp + (size_t)r0 * D_V + col) =
                        make_float2(acc[mi][ni][0], acc[mi][ni][1]);
                    *(float2*)(g_tmp + (size_t)(r0 + 8) * D_V + col) =
                        make_float2(acc[mi][ni][2], acc[mi][ni][3]);
                }
            }
        }
    };

    int t0 = blockIdx.x;
    if (t0 >= ntot) return;
    load_stage(0, t0, 0);
    int buf = 0;

    for (int t = t0; t < ntot; t += gridDim.x) {
        const int tnext = t + gridDim.x;
#pragma unroll
        for (int i = 0; i < 2; i++)
#pragma unroll
            for (int j = 0; j < 8; j++)
#pragma unroll
                for (int k = 0; k < 4; k++) acc[i][j][k] = 0.0f;

        for (int ch = 0; ch < nch; ch++) {
            const bool more_chunk = (ch + 1 < nch);
            if (more_chunk)            load_stage(buf ^ 1, t, (ch + 1) * 64);
            else if (tnext < ntot)     load_stage(buf ^ 1, tnext, 0);
            if (more_chunk || tnext < ntot) { CP_WAIT(1); }
            else                            { CP_WAIT(0); }
            __syncthreads();
            compute_stage(buf);
            buf ^= 1;
            __syncthreads();
        }
        epilogue(t);
    }
}

// ---------------- int8 scores GEMM (PERSISTENT): S~ = quant(alpha*q@k^T) ----
// CTA 128x128, 8 warps (warp 32x64), K=128 int8 in ONE 32KB stage per tile.
// mma.m16n8k32.s8; fragments via conflict-free scalar LDS.32 (SW128 swizzle).
__global__ __launch_bounds__(256, 1)
void gemm_scores_i8()
{
    constexpr int OFF_A = 0;
    constexpr int OFF_B = 16384;
    constexpr int STAGE = 32768;
    constexpr int ntn   = 64;
    constexpr int ntot  = 64 * 64;

    extern __shared__ char smem[];
    const uint32_t sb  = smem_u32(smem);
    const int tid  = threadIdx.x;
    const int wid  = tid >> 5;
    const int lane = tid & 31;

    auto load_stage = [&](int st, int t) {
        const int tm0 = (t / ntn) * 128;
        const int tn0 = (t % ntn) * 128;
#pragma unroll
        for (int it = 0; it < 8; it++) {
            int idx  = tid + it * 256;         // 0..2047 16B chunks
            int tile = idx >> 10;
            int r    = (idx >> 3) & 127;
            int g    = idx & 7;
            const signed char* src = tile
                ? g_qki + (size_t)(tn0 + r) * 256 + 128 + g * 16
                : g_qki + (size_t)(tm0 + r) * 256 + g * 16;
            uint32_t off = (uint32_t)(r * 128 + g * 16);
            off ^= (off >> 3) & 0x70;
            CP_ASYNC16(sb + st * STAGE + (tile ? OFF_B : OFF_A) + off, src);
        }
        CP_COMMIT();
    };

    const int wm = (wid & 3) * 32;
    const int wn = (wid >> 2) * 64;

    int acc[2][8][4];

    auto compute_stage = [&](int st) {
        const uint32_t base = sb + st * STAGE;
#pragma unroll
        for (int kk = 0; kk < 4; kk++) {
            const int kb = kk * 32 + (lane & 3) * 4;
            uint32_t a[2][4], b[8][2];
#pragma unroll
            for (int mi = 0; mi < 2; mi++) {
                int r0 = wm + mi * 16 + (lane >> 2);
                uint32_t o0 = (uint32_t)(r0 * 128 + kb);        o0 ^= (o0 >> 3) & 0x70;
                uint32_t o1 = (uint32_t)((r0 + 8) * 128 + kb);  o1 ^= (o1 >> 3) & 0x70;
                uint32_t o2 = (uint32_t)(r0 * 128 + kb + 16);   o2 ^= (o2 >> 3) & 0x70;
                uint32_t o3 = (uint32_t)((r0 + 8) * 128 + kb + 16); o3 ^= (o3 >> 3) & 0x70;
                LDS32(a[mi][0], base + OFF_A + o0);
                LDS32(a[mi][1], base + OFF_A + o1);
                LDS32(a[mi][2], base + OFF_A + o2);
                LDS32(a[mi][3], base + OFF_A + o3);
            }
#pragma unroll
            for (int nj = 0; nj < 8; nj++) {
                int n = wn + nj * 8 + (lane >> 2);
                uint32_t o0 = (uint32_t)(n * 128 + kb);       o0 ^= (o0 >> 3) & 0x70;
                uint32_t o1 = (uint32_t)(n * 128 + kb + 16);  o1 ^= (o1 >> 3) & 0x70;
                LDS32(b[nj][0], base + OFF_B + o0);
                LDS32(b[nj][1], base + OFF_B + o1);
            }
#pragma unroll
            for (int mi = 0; mi < 2; mi++)
#pragma unroll
                for (int nj = 0; nj < 8; nj++)
                    MMA_S8(acc[mi][nj], a[mi], b[nj][0], b[nj][1]);
        }
    };

    const int qr = lane >> 2;
    const int qc = (lane & 3) * 2;

    auto epilogue = [&](int t) {
        const int m0 = (t / ntn) * 128;
        const int n0 = (t % ntn) * 128;
        int rmax0[2] = { -1000, -1000 };
        int rmax1[2] = { -1000, -1000 };
#pragma unroll
        for (int mi = 0; mi < 2; mi++) {
            const int r0 = m0 + wm + mi * 16 + qr;
#pragma unroll
            for (int nj = 0; nj < 8; nj++) {
                const int col = n0 + wn + nj * 8 + qc;
                int s0 = min(127, max(-127, __float2int_rn(acc[mi][nj][0] * SCONV)));
                int s1 = min(127, max(-127, __float2int_rn(acc[mi][nj][1] * SCONV)));
                int s2 = min(127, max(-127, __float2int_rn(acc[mi][nj][2] * SCONV)));
                int s3 = min(127, max(-127, __float2int_rn(acc[mi][nj][3] * SCONV)));
                rmax0[mi] = max(rmax0[mi], max(s0, s1));
                rmax1[mi] = max(rmax1[mi], max(s2, s3));
                char2 p0 = { (char)s0, (char)s1 };
                char2 p1 = { (char)s2, (char)s3 };
                *(char2*)(g_Si + (size_t)r0 * N_TOK + col)       = p0;
                *(char2*)(g_Si + (size_t)(r0 + 8) * N_TOK + col) = p1;
            }
        }
#pragma unroll
        for (int mi = 0; mi < 2; mi++) {
#pragma unroll
            for (int s = 1; s < 4; s <<= 1) {
                rmax0[mi] = max(rmax0[mi], __shfl_xor_sync(0xFFFFFFFF, rmax0[mi], s));
                rmax1[mi] = max(rmax1[mi], __shfl_xor_sync(0xFFFFFFFF, rmax1[mi], s));
            }
            if ((lane & 3) == 0) {
                const int r0 = m0 + wm + mi * 16 + qr;
                atomicMax(&g_mi[r0],     rmax0[mi]);
                atomicMax(&g_mi[r0 + 8], rmax1[mi]);
            }
        }
    };

    int t0 = blockIdx.x;
    if (t0 >= ntot) return;
    load_stage(0, t0);
    int buf = 0;

    for (int t = t0; t < ntot; t += gridDim.x) {
        const int tnext = t + gridDim.x;
        if (tnext < ntot) { load_stage(buf ^ 1, tnext); CP_WAIT(1); }
        else              { CP_WAIT(0); }
        __syncthreads();
#pragma unroll
        for (int i = 0; i < 2; i++)
#pragma unroll
            for (int j = 0; j < 8; j++)
#pragma unroll
                for (int k = 0; k < 4; k++) acc[i][j][k] = 0;
        compute_stage(buf);
        buf ^= 1;
        __syncthreads();
        epilogue(t);
    }
}

// ---------------- candidate scan over int8 scores (warp-shfl scan) ----------
__global__ __launch_bounds__(256)
void candidate_scan()
{
    const int r    = blockIdx.x;
    const int tid  = threadIdx.x;
    const int lane = tid & 31;
    const int w8   = tid >> 5;
    const int thr  = g_mi[r] - THR_MARGIN;
    const int thrc = max(-128, min(127, thr));
    const unsigned thr4 = (unsigned)(thrc & 0xFF) * 0x01010101u;

    __shared__ int swarp[8];
    __shared__ int s_over;
    if (tid == 0) s_over = 0;
    __syncthreads();

    const uint4* row = (const uint4*)(g_Si + (size_t)r * N_TOK);
    int lj[8]; int lc = 0, over = 0;
#pragma unroll
    for (int it = 0; it < 2; it++) {
        int v4 = tid + it * 256;          // each uint4 = 16 int8
        uint4 u = row[v4];
        unsigned w[4] = { u.x, u.y, u.z, u.w };
        int jb = v4 * 16;
#pragma unroll
        for (int k = 0; k < 4; k++) {
            unsigned msk = __vcmpgts4(w[k], thr4);
            if (msk) {
#pragma unroll
                for (int e = 0; e < 4; e++) {
                    if (msk & (0xFFu << (8 * e))) {
                        if (lc < 8) lj[lc] = jb + k * 4 + e;
                        else over = 1;
                        lc++;
                    }
                }
            }
        }
    }
    if (over) atomicOr(&s_over, 1);

    // warp inclusive scan of lc
    int inc = lc;
#pragma unroll
    for (int s = 1; s < 32; s <<= 1) {
        int v = __shfl_up_sync(0xFFFFFFFF, inc, s);
        if (lane >= s) inc += v;
    }
    if (lane == 31) swarp[w8] = inc;
    __syncthreads();

    int base = 0, total = 0;
#pragma unroll
    for (int w = 0; w < 8; w++) {
        int sv = swarp[w];
        if (w < w8) base += sv;
        total += sv;
    }
    const int myoff = base + inc - lc;
    const int dense = (total > CAP) || (s_over != 0);

    if (!dense) {
        const int n = (lc < 8) ? lc : 8;
        for (int i = 0; i < n; i++)
            g_cand[(size_t)r * CAP + myoff + i] =
                make_float2(__int_as_float(lj[i]), 0.0f);
    }
    if (tid == 0) g_cnt[r] = dense ? (CAP + 1) : total;
}

// ---------------- exact softmax over candidates (fp32 q,k) ------------------
__global__ __launch_bounds__(128)
void exact_softmax()
{
    const int r    = blockIdx.x;
    const int tid  = threadIdx.x;
    const int wrp  = tid >> 5;
    const int lane = tid & 31;
    const int cnt  = g_cnt[r];
    if (cnt > CAP) return;

    __shared__ float ss[CAP];
    __shared__ float smax, ssum;

    for (int c = wrp; c < cnt; c += 4) {
        int j = __float_as_int(g_cand[(size_t)r * CAP + c].x);
        const float4 qf = *(const float4*)(g_qk + (size_t)r * 256 + lane * 4);
        const float4 kf = *(const float4*)(g_qk + (size_t)j * 256 + 128 + lane * 4);
        float p = qf.x * kf.x + qf.y * kf.y + qf.z * kf.z + qf.w * kf.w;
#pragma unroll
        for (int s = 16; s; s >>= 1) p += __shfl_xor_sync(0xFFFFFFFF, p, s);
        if (lane == 0) ss[c] = ALPHA * p;
    }
    __syncthreads();

    if (tid == 0) {
        float mx = -1e30f;
        for (int c = 0; c < cnt; c++) mx = fmaxf(mx, ss[c]);
        float l = 0.0f;
        for (int c = 0; c < cnt; c++) l += __expf(ss[c] - mx);
        smax = mx; ssum = l;
    }
    __syncthreads();

    const float mx = smax, invl = 1.0f / ssum;
    for (int c = tid; c < cnt; c += 128)
        g_cand[(size_t)r * CAP + c].y = __expf(ss[c] - mx) * invl;
}

// ---------------- sparse attn@v + fused residual + LN1 ----------------------
__global__ __launch_bounds__(64)
void attn_av_ln(const float* __restrict__ x)
{
    const int r   = blockIdx.x;
    const int tid = threadIdx.x;
    const int cnt = g_cnt[r];
    const int d   = tid * 16;

    float4 a0 = make_float4(0, 0, 0, 0), a1 = a0, a2 = a0, a3 = a0;

    if (cnt <= CAP) {
        const float2* cl = g_cand + (size_t)r * CAP;
        for (int i = 0; i < cnt; i++) {
            float2 c = cl[i];
            int   j = __float_as_int(c.x);
            float w = c.y;
            const float* vr = g_v + (size_t)j * D_V + d;
            float4 v0 = *(const float4*)(vr);
            float4 v1 = *(const float4*)(vr + 4);
            float4 v2 = *(const float4*)(vr + 8);
            float4 v3 = *(const float4*)(vr + 12);
            a0.x += w * v0.x; a0.y += w * v0.y; a0.z += w * v0.z; a0.w += w * v0.w;
            a1.x += w * v1.x; a1.y += w * v1.y; a1.z += w * v1.z; a1.w += w * v1.w;
            a2.x += w * v2.x; a2.y += w * v2.y; a2.z += w * v2.z; a2.w += w * v2.w;
            a3.x += w * v3.x; a3.y += w * v3.y; a3.z += w * v3.z; a3.w += w * v3.w;
        }
    } else {
        __shared__ float sw[64];
        __shared__ float sred[64];
        const float* qf = g_qk + (size_t)r * 256;
        float mx = -1e30f;
        for (int jb = 0; jb < N_TOK; jb += 64) {
            const float* kf = g_qk + (size_t)(jb + tid) * 256 + 128;
            float s = 0.0f;
            for (int e = 0; e < 128; e++) s += qf[e] * kf[e];
            mx = fmaxf(mx, ALPHA * s);
        }
        sred[tid] = mx;
        __syncthreads();
        for (int st = 32; st; st >>= 1) {
            if (tid < st) sred[tid] = fmaxf(sred[tid], sred[tid + st]);
            __syncthreads();
        }
        mx = sred[0];
        float l = 0.0f;
        for (int jb = 0; jb < N_TOK; jb += 64) {
            const float* kf = g_qk + (size_t)(jb + tid) * 256 + 128;
            float s = 0.0f;
            for (int e = 0; e < 128; e++) s += qf[e] * kf[e];
            sw[tid] = __expf(ALPHA * s - mx);
            __syncthreads();
            for (int jj = 0; jj < 64; jj++) {
                float w = sw[jj];
                l += w;
                const float* vr = g_v + (size_t)(jb + jj) * D_V + d;
                float4 v0 = *(const float4*)(vr);
                float4 v1 = *(const float4*)(vr + 4);
                float4 v2 = *(const float4*)(vr + 8);
                float4 v3 = *(const float4*)(vr + 12);
                a0.x += w * v0.x; a0.y += w * v0.y; a0.z += w * v0.z; a0.w += w * v0.w;
                a1.x += w * v1.x; a1.y += w * v1.y; a1.z += w * v1.z; a1.w += w * v1.w;
                a2.x += w * v2.x; a2.y += w * v2.y; a2.z += w * v2.z; a2.w += w * v2.w;
                a3.x += w * v3.x; a3.y += w * v3.y; a3.z += w * v3.z; a3.w += w * v3.w;
            }
            __syncthreads();
        }
        const float inv = 1.0f / l;
        a0.x *= inv; a0.y *= inv; a0.z *= inv; a0.w *= inv;
        a1.x *= inv; a1.y *= inv; a1.z *= inv; a1.w *= inv;
        a2.x *= inv; a2.y *= inv; a2.z *= inv; a2.w *= inv;
        a3.x *= inv; a3.y *= inv; a3.z *= inv; a3.w *= inv;
    }

    float* out = g_sa + (size_t)r * D_V + d;
    *(float4*)(out)      = a0;
    *(float4*)(out + 4)  = a1;
    *(float4*)(out + 8)  = a2;
    *(float4*)(out + 12) = a3;

    // fused LN1: h = LN(x + sa) -> bf16 hi/lo
    {
        __shared__ float2 r2[64];
        float y[16];
        const float* xp = x + (size_t)r * D_IN + d;
        float4 x0 = *(const float4*)(xp);
        float4 x1 = *(const float4*)(xp + 4);
        float4 x2 = *(const float4*)(xp + 8);
        float4 x3 = *(const float4*)(xp + 12);
        y[0]=x0.x+a0.x; y[1]=x0.y+a0.y; y[2]=x0.z+a0.z; y[3]=x0.w+a0.w;
        y[4]=x1.x+a1.x; y[5]=x1.y+a1.y; y[6]=x1.z+a1.z; y[7]=x1.w+a1.w;
        y[8]=x2.x+a2.x; y[9]=x2.y+a2.y; y[10]=x2.z+a2.z; y[11]=x2.w+a2.w;
        y[12]=x3.x+a3.x; y[13]=x3.y+a3.y; y[14]=x3.z+a3.z; y[15]=x3.w+a3.w;
        float s = 0.0f, sq = 0.0f;
#pragma unroll
        for (int e = 0; e < 16; e++) { s += y[e]; sq += y[e] * y[e]; }
        __syncthreads();
        r2[tid] = make_float2(s, sq);
        __syncthreads();
        for (int st = 32; st; st >>= 1) {
            if (tid < st) {
                r2[tid].x += r2[tid + st].x;
                r2[tid].y += r2[tid + st].y;
            }
            __syncthreads();
        }
        const float mean = r2[0].x * (1.0f / (float)D_IN);
        const float var  = r2[0].y * (1.0f / (float)D_IN) - mean * mean;
        const float rstd = rsqrtf(var + 1e-5f);
        size_t base = (size_t)r * D_IN + d;
#pragma unroll
        for (int e = 0; e < 16; e++) {
            float o = (y[e] - mean) * rstd;
            split_bf16(o, g_hh[base + e], g_hl[base + e]);
        }
    }
}

// ---------------- final residual + LayerNorm: out = LN(sa + tmp) ------------
__global__ __launch_bounds__(256)
void ln_final(float* __restrict__ ext_out)
{
    const int r   = blockIdx.x;
    const int tid = threadIdx.x;

    const float4 av = *(const float4*)(g_sa  + (size_t)r * D_V + tid * 4);
    const float4 bv = *(const float4*)(g_tmp + (size_t)r * D_V + tid * 4);
    float4 y = make_float4(av.x + bv.x, av.y + bv.y, av.z + bv.z, av.w + bv.w);

    float s  = y.x + y.y + y.z + y.w;
    float sq = y.x * y.x + y.y * y.y + y.z * y.z + y.w * y.w;

    __shared__ float2 red2[256];
    red2[tid] = make_float2(s, sq);
    __syncthreads();
    for (int st = 128; st > 0; st >>= 1) {
        if (tid < st) {
            red2[tid].x += red2[tid + st].x;
            red2[tid].y += red2[tid + st].y;
        }
        __syncthreads();
    }
    const float mean = red2[0].x * (1.0f / (float)D_V);
    const float var  = red2[0].y * (1.0f / (float)D_V) - mean * mean;
    const float rstd = rsqrtf(var + 1e-5f);

    *(float4*)(ext_out + (size_t)r * D_V + tid * 4) =
        make_float4((y.x - mean) * rstd, (y.y - mean) * rstd,
                    (y.z - mean) * rstd, (y.w - mean) * rstd);
}

// ---------------- launch sequence ----------------
extern "C" void kernel_launch(void* const* d_in, const int* in_sizes, int n_in,
                              void* d_out, int out_size)
{
    const float* x  = (const float*)d_in[0];
    const float* Wq = (const float*)d_in[1];
    const float* Wk = (const float*)d_in[2];
    const float* Wv = (const float*)d_in[3];
    const float* Wl = (const float*)d_in[4];
    float* out = (float*)d_out;

    const int SMEM_X3 = 2 * (2 * 64 * 128 + 2 * TILE_B);   // 98304
    const int SMEM_I8 = 2 * 32768;                         // 65536
    cudaFuncSetAttribute(gemm_mma<0>, cudaFuncAttributeMaxDynamicSharedMemorySize, SMEM_X3);
    cudaFuncSetAttribute(gemm_mma<2>, cudaFuncAttributeMaxDynamicSharedMemorySize, SMEM_X3);
    cudaFuncSetAttribute(gemm_scores_i8, cudaFuncAttributeMaxDynamicSharedMemorySize, SMEM_I8);

    prep_all<<<512, 256>>>(x, Wq, Wk, Wv, Wl);

    gemm_mma<0><<<2 * NSM, 128, SMEM_X3>>>();   // qkv (bf16x3, 2 CTAs/SM)
    gemm_scores_i8<<<NSM, 256, SMEM_I8>>>();    // int8 scores + row max

    candidate_scan<<<N_TOK, 256>>>();
    exact_softmax<<<N_TOK, 128>>>();
    attn_av_ln<<<N_TOK, 64>>>(x);               // sparse AV + fused LN1

    gemm_mma<2><<<2 * NSM, 128, SMEM_X3>>>();   // output projection (bf16x3, 2 CTAs/SM)

    ln_final<<<N_TOK, 256>>>(out);
}

// round 17
// speedup vs baseline: 1.1425x; 1.1425x over previous
#include <cuda_runtime.h>
#include <cuda_bf16.h>
#include <cstdint>
#include <math.h>

// Problem dims (fixed by the dataset)
#define N_TOK 8192
#define D_IN  1024
#define D_QK  128
#define D_V   1024
#define D_W1  1280
#define CAP   1024
#define NSM   148
#define ALPHA 11.313708498984760f   // sqrt(128)
#define THR_MARGIN 24               // int8 score units (x2 = logit units)

// ---------------- scratch (static device globals; no allocs) ----------------
static __device__ __align__(16) __nv_bfloat16 g_xh [(size_t)N_TOK * D_IN];
static __device__ __align__(16) __nv_bfloat16 g_xl [(size_t)N_TOK * D_IN];
static __device__ __align__(16) __nv_bfloat16 g_W1h[(size_t)D_W1 * D_IN];
static __device__ __align__(16) __nv_bfloat16 g_W1l[(size_t)D_W1 * D_IN];
static __device__ __align__(16) __nv_bfloat16 g_Wlh[(size_t)D_V * D_IN];
static __device__ __align__(16) __nv_bfloat16 g_Wll[(size_t)D_V * D_IN];
static __device__ __align__(16) __nv_bfloat16 g_qkh[(size_t)N_TOK * 256];  // bf16 q|k
static __device__ __align__(16) float         g_qk [(size_t)N_TOK * 256];  // fp32 q|k
static __device__ __align__(16) __nv_bfloat16 g_hh [(size_t)N_TOK * D_IN];
static __device__ __align__(16) __nv_bfloat16 g_hl [(size_t)N_TOK * D_IN];
static __device__ float  g_v  [(size_t)N_TOK * D_V];
static __device__ __align__(16) signed char   g_Si[(size_t)N_TOK * N_TOK]; // int8 scores (s/2)
static __device__ int    g_mi [N_TOK];                                     // int8-domain row max
static __device__ int    g_cnt[N_TOK];
static __device__ float2 g_cand[(size_t)N_TOK * CAP];
static __device__ float  g_sa [(size_t)N_TOK * D_V];
static __device__ float  g_tmp[(size_t)N_TOK * D_V];

// ---------------- helpers ----------------
__device__ __forceinline__ uint32_t smem_u32(const void* p) {
    uint32_t a;
    asm("{ .reg .u64 t; cvta.to.shared.u64 t, %1; cvt.u32.u64 %0, t; }" : "=r"(a) : "l"(p));
    return a;
}
__device__ __forceinline__ void split_bf16(float v, __nv_bfloat16& h, __nv_bfloat16& l) {
    h = __float2bfloat16(v);
    l = __float2bfloat16(v - __bfloat162float(h));
}
__device__ __forceinline__ int quant_s(float s) {
    int u = __float2int_rn(s * 0.5f);
    return min(127, max(-127, u));
}

#define LDSM_X4(r, addr)                                                        \
    asm volatile("ldmatrix.sync.aligned.m8n8.x4.shared.b16 {%0,%1,%2,%3}, [%4];" \
        : "=r"((r)[0]), "=r"((r)[1]), "=r"((r)[2]), "=r"((r)[3]) : "r"(addr))

#define MMA_BF16(c, a, b)                                                       \
    asm volatile("mma.sync.aligned.m16n8k16.row.col.f32.bf16.bf16.f32 "         \
        "{%0,%1,%2,%3}, {%4,%5,%6,%7}, {%8,%9}, {%0,%1,%2,%3};"                 \
        : "+f"((c)[0]), "+f"((c)[1]), "+f"((c)[2]), "+f"((c)[3])                \
        : "r"((a)[0]), "r"((a)[1]), "r"((a)[2]), "r"((a)[3]),                   \
          "r"((b)[0]), "r"((b)[1]))

#define CP_ASYNC16(dst, src) \
    asm volatile("cp.async.cg.shared.global [%0], [%1], 16;" :: "r"(dst), "l"(src))
#define CP_COMMIT()  asm volatile("cp.async.commit_group;")
#define CP_WAIT(n)   asm volatile("cp.async.wait_group %0;" :: "n"(n))

// ---------------- combined prep: weight/x bf16 hi-lo split + init -----------
__global__ void prep_all(const float* __restrict__ x,
                         const float* __restrict__ Wq, const float* __restrict__ Wk,
                         const float* __restrict__ Wv, const float* __restrict__ Wl)
{
    const int stride = gridDim.x * blockDim.x;
    int g = blockIdx.x * blockDim.x + threadIdx.x;
    for (int i = g; i < D_W1 * D_IN; i += stride) {
        int r = i >> 10, c = i & 1023;
        float v;
        if (r < 128)      v = Wq[r * D_IN + c];
        else if (r < 256) v = Wk[(r - 128) * D_IN + c];
        else              v = Wv[(r - 256) * D_IN + c];
        split_bf16(v, g_W1h[i], g_W1l[i]);
    }
    for (int i = g; i < D_V * D_IN; i += stride)
        split_bf16(Wl[i], g_Wlh[i], g_Wll[i]);
    for (int i = g; i < N_TOK * D_IN; i += stride)
        split_bf16(x[i], g_xh[i], g_xl[i]);
    for (int i = g; i < N_TOK; i += stride)
        g_mi[i] = -(1 << 30);
}

// ---------------- bf16 tensor-core GEMM (PERSISTENT) ------------------------
// MODE 0/2 (bf16x3): CTA 64x128, 4 warps, 2 CTAs/SM (R14/R15 measured-best).
// MODE 1   (bf16x1): CTA 128x128, 8 warps; epilogue emits int8 scores.
#define TILE_B 16384

template<int MODE>
__global__ __launch_bounds__(256, 1)
void gemm_mma()
{
    constexpr int CTA_M  = (MODE == 1) ? 128 : 64;
    constexpr int A_TILE = CTA_M * 128;
    constexpr int OFF_AH = 0;
    constexpr int OFF_AL = A_TILE;
    constexpr int OFF_BH = (MODE == 1) ? A_TILE : 2 * A_TILE;
    constexpr int OFF_BL = OFF_BH + TILE_B;
    constexpr int STAGE  = (MODE == 1) ? (A_TILE + TILE_B)
                                       : (2 * A_TILE + 2 * TILE_B);

    extern __shared__ char smem[];
    const uint32_t sb  = smem_u32(smem);
    const int tid  = threadIdx.x;
    const int wid  = tid >> 5;
    const int lane = tid & 31;

    const __nv_bfloat16 *Ah, *Al = nullptr, *Bh, *Bl = nullptr;
    constexpr int lda = (MODE == 1) ? 256 : 1024;
    constexpr int K   = (MODE == 1) ? 128 : 1024;
    constexpr int ntn = (MODE == 0) ? 10 : (MODE == 1 ? 64 : 8);
    if constexpr (MODE == 0)      { Ah = g_xh;  Al = g_xl; Bh = g_W1h;       Bl = g_W1l; }
    else if constexpr (MODE == 1) { Ah = g_qkh;            Bh = g_qkh + 128; }
    else                          { Ah = g_hh;  Al = g_hl; Bh = g_Wlh;       Bl = g_Wll; }

    constexpr int nch  = K / 64;
    constexpr int ntot = ntn * (N_TOK / CTA_M);

    auto load_stage = [&](int st, int t, int k0) {
        const int tm0 = (t / ntn) * CTA_M;
        const int tn0 = (t % ntn) * 128;
        if constexpr (MODE == 1) {
            const __nv_bfloat16* bs[2] = { Ah + (size_t)tm0 * lda,
                                           Bh + (size_t)tn0 * lda };
#pragma unroll
            for (int it = 0; it < 8; it++) {
                int idx  = tid + it * 256;
                int tile = idx >> 10;
                int r    = (idx >> 3) & 127;
                int g    = idx & 7;
                const __nv_bfloat16* src = bs[tile] + (size_t)r * lda + k0 + g * 8;
                uint32_t off = (uint32_t)(r * 128 + g * 16);
                off ^= (off >> 3) & 0x70;
                CP_ASYNC16(sb + st * STAGE + tile * TILE_B + off, src);
            }
        } else {
            const __nv_bfloat16* bsA[2] = { Ah + (size_t)tm0 * lda,
                                            Al + (size_t)tm0 * lda };
            const __nv_bfloat16* bsB[2] = { Bh + (size_t)tn0 * lda,
                                            Bl + (size_t)tn0 * lda };
#pragma unroll
            for (int it = 0; it < 24; it++) {
                int idx = tid + it * 128;
                const __nv_bfloat16* src;
                uint32_t dst;
                if (idx < 1024) {
                    int half = idx >> 9;
                    int r    = (idx >> 3) & 63;
                    int g    = idx & 7;
                    src = bsA[half] + (size_t)r * lda + k0 + g * 8;
                    uint32_t off = (uint32_t)(r * 128 + g * 16);
                    off ^= (off >> 3) & 0x70;
                    dst = (half ? OFF_AL : OFF_AH) + off;
                } else {
                    int idx2 = idx - 1024;
                    int half = idx2 >> 10;
                    int r    = (idx2 >> 3) & 127;
                    int g    = idx2 & 7;
                    src = bsB[half] + (size_t)r * lda + k0 + g * 8;
                    uint32_t off = (uint32_t)(r * 128 + g * 16);
                    off ^= (off >> 3) & 0x70;
                    dst = (half ? OFF_BL : OFF_BH) + off;
                }
                CP_ASYNC16(sb + st * STAGE + dst, src);
            }
        }
        CP_COMMIT();
    };

    const int wm = (MODE == 1) ? (wid & 3) * 32 : (wid & 1) * 32;
    const int wn = (MODE == 1) ? (wid >> 2) * 64 : (wid >> 1) * 64;

    float acc[2][8][4];

    auto load_frags = [&](uint32_t base, int k16,
                          uint32_t (*ah)[4], uint32_t (*al)[4],
                          uint32_t (*bh)[4], uint32_t (*bl)[4]) {
#pragma unroll
        for (int mi = 0; mi < 2; mi++) {
            int row = wm + mi * 16 + (lane & 15);
            int c16 = k16 * 2 + (lane >> 4);
            uint32_t off = (uint32_t)(row * 128 + c16 * 16);
            off ^= (off >> 3) & 0x70;
            LDSM_X4(ah[mi], base + OFF_AH + off);
            if constexpr (MODE != 1) LDSM_X4(al[mi], base + OFF_AL + off);
        }
#pragma unroll
        for (int nj = 0; nj < 4; nj++) {
            int row = wn + nj * 16 + (lane & 7) + ((lane >> 4) << 3);
            int c16 = k16 * 2 + ((lane >> 3) & 1);
            uint32_t off = (uint32_t)(row * 128 + c16 * 16);
            off ^= (off >> 3) & 0x70;
            LDSM_X4(bh[nj], base + OFF_BH + off);
            if constexpr (MODE != 1) LDSM_X4(bl[nj], base + OFF_BL + off);
        }
    };

    auto compute_stage = [&](int st) {
        const uint32_t base = sb + st * STAGE;
        uint32_t ah[2][2][4], al[2][2][4], bh[2][4][4], bl[2][4][4];
        load_frags(base, 0, ah[0], al[0], bh[0], bl[0]);
#pragma unroll
        for (int k16 = 0; k16 < 4; k16++) {
            const int cur = k16 & 1;
#pragma unroll
            for (int mi = 0; mi < 2; mi++)
#pragma unroll
                for (int nj = 0; nj < 4; nj++) {
                    MMA_BF16(acc[mi][nj * 2],     ah[cur][mi], (bh[cur][nj] + 0));
                    MMA_BF16(acc[mi][nj * 2 + 1], ah[cur][mi], (bh[cur][nj] + 2));
                }
            if (k16 < 3)
                load_frags(base, k16 + 1, ah[cur ^ 1], al[cur ^ 1],
                           bh[cur ^ 1], bl[cur ^ 1]);
            if constexpr (MODE != 1) {
#pragma unroll
                for (int mi = 0; mi < 2; mi++)
#pragma unroll
                    for (int nj = 0; nj < 4; nj++) {
                        MMA_BF16(acc[mi][nj * 2],     ah[cur][mi], (bl[cur][nj] + 0));
                        MMA_BF16(acc[mi][nj * 2 + 1], ah[cur][mi], (bl[cur][nj] + 2));
                    }
#pragma unroll
                for (int mi = 0; mi < 2; mi++)
#pragma unroll
                    for (int nj = 0; nj < 4; nj++) {
                        MMA_BF16(acc[mi][nj * 2],     al[cur][mi], (bh[cur][nj] + 0));
                        MMA_BF16(acc[mi][nj * 2 + 1], al[cur][mi], (bh[cur][nj] + 2));
                    }
            }
        }
    };

    const int qr = lane >> 2;
    const int qc = (lane & 3) * 2;

    auto epilogue = [&](int t) {
        const int m0 = (t / ntn) * CTA_M;
        const int n0 = (t % ntn) * 128;
        if constexpr (MODE == 1) {
            float rmax0[2] = { -1e30f, -1e30f };
            float rmax1[2] = { -1e30f, -1e30f };
#pragma unroll
            for (int mi = 0; mi < 2; mi++) {
                const int r0 = m0 + wm + mi * 16 + qr;
#pragma unroll
                for (int ni = 0; ni < 8; ni++) {
                    const int col = n0 + wn + ni * 8 + qc;
                    float c0 = ALPHA * acc[mi][ni][0], c1 = ALPHA * acc[mi][ni][1];
                    float c2 = ALPHA * acc[mi][ni][2], c3 = ALPHA * acc[mi][ni][3];
                    rmax0[mi] = fmaxf(rmax0[mi], fmaxf(c0, c1));
                    rmax1[mi] = fmaxf(rmax1[mi], fmaxf(c2, c3));
                    char2 p0 = { (char)quant_s(c0), (char)quant_s(c1) };
                    char2 p1 = { (char)quant_s(c2), (char)quant_s(c3) };
                    *(char2*)(g_Si + (size_t)r0 * N_TOK + col)       = p0;
                    *(char2*)(g_Si + (size_t)(r0 + 8) * N_TOK + col) = p1;
                }
            }
#pragma unroll
            for (int mi = 0; mi < 2; mi++) {
#pragma unroll
                for (int s = 1; s < 4; s <<= 1) {
                    rmax0[mi] = fmaxf(rmax0[mi], __shfl_xor_sync(0xFFFFFFFF, rmax0[mi], s));
                    rmax1[mi] = fmaxf(rmax1[mi], __shfl_xor_sync(0xFFFFFFFF, rmax1[mi], s));
                }
                if ((lane & 3) == 0) {
                    const int r0 = m0 + wm + mi * 16 + qr;
                    atomicMax(&g_mi[r0],     quant_s(rmax0[mi]));
                    atomicMax(&g_mi[r0 + 8], quant_s(rmax1[mi]));
                }
            }
        } else if constexpr (MODE == 0) {
#pragma unroll
            for (int mi = 0; mi < 2; mi++) {
                const int r0 = m0 + wm + mi * 16 + qr;
#pragma unroll
                for (int ni = 0; ni < 8; ni++) {
                    const int col = n0 + wn + ni * 8 + qc;
                    if (col < 256) {
#pragma unroll
                        for (int half = 0; half < 2; half++) {
                            const int rr = r0 + half * 8;
                            float v0 = acc[mi][ni][half * 2 + 0];
                            float v1 = acc[mi][ni][half * 2 + 1];
                            *(float2*)(g_qk + (size_t)rr * 256 + col) = make_float2(v0, v1);
                            *(__nv_bfloat162*)(g_qkh + (size_t)rr * 256 + col) =
                                __nv_bfloat162(__float2bfloat16(v0), __float2bfloat16(v1));
                        }
                    } else {
                        const int vc = col - 256;
                        *(float2*)(g_v + (size_t)r0 * D_V + vc) =
                            make_float2(acc[mi][ni][0], acc[mi][ni][1]);
                        *(float2*)(g_v + (size_t)(r0 + 8) * D_V + vc) =
                            make_float2(acc[mi][ni][2], acc[mi][ni][3]);
                    }
                }
            }
        } else {
#pragma unroll
            for (int mi = 0; mi < 2; mi++) {
                const int r0 = m0 + wm + mi * 16 + qr;
#pragma unroll
                for (int ni = 0; ni < 8; ni++) {
                    const int col = n0 + wn + ni * 8 + qc;
                    *(float2*)(g_tmp + (size_t)r0 * D_V + col) =
                        make_float2(acc[mi][ni][0], acc[mi][ni][1]);
                    *(float2*)(g_tmp + (size_t)(r0 + 8) * D_V + col) =
                        make_float2(acc[mi][ni][2], acc[mi][ni][3]);
                }
            }
        }
    };

    int t0 = blockIdx.x;
    if (t0 >= ntot) return;
    load_stage(0, t0, 0);
    int buf = 0;

    for (int t = t0; t < ntot; t += gridDim.x) {
        const int tnext = t + gridDim.x;
#pragma unroll
        for (int i = 0; i < 2; i++)
#pragma unroll
            for (int j = 0; j < 8; j++)
#pragma unroll
                for (int k = 0; k < 4; k++) acc[i][j][k] = 0.0f;

        for (int ch = 0; ch < nch; ch++) {
            const bool more_chunk = (ch + 1 < nch);
            if (more_chunk)            load_stage(buf ^ 1, t, (ch + 1) * 64);
            else if (tnext < ntot)     load_stage(buf ^ 1, tnext, 0);
            if (more_chunk || tnext < ntot) { CP_WAIT(1); }
            else                            { CP_WAIT(0); }
            __syncthreads();
            compute_stage(buf);
            buf ^= 1;
            __syncthreads();
        }
        epilogue(t);
    }
}

// ---------------- fused candidate scan + exact softmax ----------------------
// Scan phase identical to R15's candidate_scan (int8, __vcmpgts4, 256-thread
// prefix scan); candidates stay in SMEM; softmax phase identical to R15's
// exact_softmax (warp-per-candidate fp32 dot, 8 warps instead of 4).
__global__ __launch_bounds__(256)
void cand_softmax()
{
    const int r    = blockIdx.x;
    const int tid  = threadIdx.x;
    const int wrp  = tid >> 5;
    const int lane = tid & 31;
    const int thr  = g_mi[r] - THR_MARGIN;
    const int thrc = max(-128, min(127, thr));
    const unsigned thr4 = (unsigned)(thrc & 0xFF) * 0x01010101u;

    __shared__ int   sc[256];
    __shared__ int   s_over;
    __shared__ int   s_cand[CAP];
    __shared__ float ss[CAP];
    __shared__ float smax, ssum;
    if (tid == 0) s_over = 0;
    __syncthreads();

    const uint4* row = (const uint4*)(g_Si + (size_t)r * N_TOK);
    int lj[8]; int lc = 0, over = 0;
#pragma unroll
    for (int it = 0; it < 2; it++) {
        int v4 = tid + it * 256;          // each uint4 = 16 int8
        uint4 u = row[v4];
        unsigned w[4] = { u.x, u.y, u.z, u.w };
        int jb = v4 * 16;
#pragma unroll
        for (int k = 0; k < 4; k++) {
            unsigned msk = __vcmpgts4(w[k], thr4);
            if (msk) {
#pragma unroll
                for (int e = 0; e < 4; e++) {
                    if (msk & (0xFFu << (8 * e))) {
                        if (lc < 8) lj[lc] = jb + k * 4 + e;
                        else over = 1;
                        lc++;
                    }
                }
            }
        }
    }
    if (over) atomicOr(&s_over, 1);

    sc[tid] = lc;
    __syncthreads();
    for (int off = 1; off < 256; off <<= 1) {
        int tsc = (tid >= off) ? sc[tid - off] : 0;
        __syncthreads();
        sc[tid] += tsc;
        __syncthreads();
    }
    const int total = sc[255];
    const int myoff = sc[tid] - lc;
    const int dense = (total > CAP) || (s_over != 0);

    if (dense) {
        if (tid == 0) g_cnt[r] = CAP + 1;
        return;
    }

    {
        const int n = (lc < 8) ? lc : 8;
        for (int i = 0; i < n; i++) s_cand[myoff + i] = lj[i];
    }
    if (tid == 0) g_cnt[r] = total;
    __syncthreads();

    const int cnt = total;

    // exact fp32 logits, warp per candidate (identical math to R15)
    for (int c = wrp; c < cnt; c += 8) {
        int j = s_cand[c];
        const float4 qf = *(const float4*)(g_qk + (size_t)r * 256 + lane * 4);
        const float4 kf = *(const float4*)(g_qk + (size_t)j * 256 + 128 + lane * 4);
        float p = qf.x * kf.x + qf.y * kf.y + qf.z * kf.z + qf.w * kf.w;
#pragma unroll
        for (int s = 16; s; s >>= 1) p += __shfl_xor_sync(0xFFFFFFFF, p, s);
        if (lane == 0) ss[c] = ALPHA * p;
    }
    __syncthreads();

    if (tid == 0) {
        float mx = -1e30f;
        for (int c = 0; c < cnt; c++) mx = fmaxf(mx, ss[c]);
        float l = 0.0f;
        for (int c = 0; c < cnt; c++) l += __expf(ss[c] - mx);
        smax = mx; ssum = l;
    }
    __syncthreads();

    const float mx = smax, invl = 1.0f / ssum;
    for (int c = tid; c < cnt; c += 256)
        g_cand[(size_t)r * CAP + c] =
            make_float2(__int_as_float(s_cand[c]), __expf(ss[c] - mx) * invl);
}

// ---------------- sparse attn@v + fused residual + LN1 ----------------------
__global__ __launch_bounds__(64)
void attn_av_ln(const float* __restrict__ x)
{
    const int r   = blockIdx.x;
    const int tid = threadIdx.x;
    const int cnt = g_cnt[r];
    const int d   = tid * 16;

    float4 a0 = make_float4(0, 0, 0, 0), a1 = a0, a2 = a0, a3 = a0;

    if (cnt <= CAP) {
        const float2* cl = g_cand + (size_t)r * CAP;
        for (int i = 0; i < cnt; i++) {
            float2 c = cl[i];
            int   j = __float_as_int(c.x);
            float w = c.y;
            const float* vr = g_v + (size_t)j * D_V + d;
            float4 v0 = *(const float4*)(vr);
            float4 v1 = *(const float4*)(vr + 4);
            float4 v2 = *(const float4*)(vr + 8);
            float4 v3 = *(const float4*)(vr + 12);
            a0.x += w * v0.x; a0.y += w * v0.y; a0.z += w * v0.z; a0.w += w * v0.w;
            a1.x += w * v1.x; a1.y += w * v1.y; a1.z += w * v1.z; a1.w += w * v1.w;
            a2.x += w * v2.x; a2.y += w * v2.y; a2.z += w * v2.z; a2.w += w * v2.w;
            a3.x += w * v3.x; a3.y += w * v3.y; a3.z += w * v3.z; a3.w += w * v3.w;
        }
    } else {
        __shared__ float sw[64];
        __shared__ float sred[64];
        const float* qf = g_qk + (size_t)r * 256;
        float mx = -1e30f;
        for (int jb = 0; jb < N_TOK; jb += 64) {
            const float* kf = g_qk + (size_t)(jb + tid) * 256 + 128;
            float s = 0.0f;
            for (int e = 0; e < 128; e++) s += qf[e] * kf[e];
            mx = fmaxf(mx, ALPHA * s);
        }
        sred[tid] = mx;
        __syncthreads();
        for (int st = 32; st; st >>= 1) {
            if (tid < st) sred[tid] = fmaxf(sred[tid], sred[tid + st]);
            __syncthreads();
        }
        mx = sred[0];
        float l = 0.0f;
        for (int jb = 0; jb < N_TOK; jb += 64) {
            const float* kf = g_qk + (size_t)(jb + tid) * 256 + 128;
            float s = 0.0f;
            for (int e = 0; e < 128; e++) s += qf[e] * kf[e];
            sw[tid] = __expf(ALPHA * s - mx);
            __syncthreads();
            for (int jj = 0; jj < 64; jj++) {
                float w = sw[jj];
                l += w;
                const float* vr = g_v + (size_t)(jb + jj) * D_V + d;
                float4 v0 = *(const float4*)(vr);
                float4 v1 = *(const float4*)(vr + 4);
                float4 v2 = *(const float4*)(vr + 8);
                float4 v3 = *(const float4*)(vr + 12);
                a0.x += w * v0.x; a0.y += w * v0.y; a0.z += w * v0.z; a0.w += w * v0.w;
                a1.x += w * v1.x; a1.y += w * v1.y; a1.z += w * v1.z; a1.w += w * v1.w;
                a2.x += w * v2.x; a2.y += w * v2.y; a2.z += w * v2.z; a2.w += w * v2.w;
                a3.x += w * v3.x; a3.y += w * v3.y; a3.z += w * v3.z; a3.w += w * v3.w;
            }
            __syncthreads();
        }
        const float inv = 1.0f / l;
        a0.x *= inv; a0.y *= inv; a0.z *= inv; a0.w *= inv;
        a1.x *= inv; a1.y *= inv; a1.z *= inv; a1.w *= inv;
        a2.x *= inv; a2.y *= inv; a2.z *= inv; a2.w *= inv;
        a3.x *= inv; a3.y *= inv; a3.z *= inv; a3.w *= inv;
    }

    float* out = g_sa + (size_t)r * D_V + d;
    *(float4*)(out)      = a0;
    *(float4*)(out + 4)  = a1;
    *(float4*)(out + 8)  = a2;
    *(float4*)(out + 12) = a3;

    // fused LN1: h = LN(x + sa) -> bf16 hi/lo
    {
        __shared__ float2 r2[64];
        float y[16];
        const float* xp = x + (size_t)r * D_IN + d;
        float4 x0 = *(const float4*)(xp);
        float4 x1 = *(const float4*)(xp + 4);
        float4 x2 = *(const float4*)(xp + 8);
        float4 x3 = *(const float4*)(xp + 12);
        y[0]=x0.x+a0.x; y[1]=x0.y+a0.y; y[2]=x0.z+a0.z; y[3]=x0.w+a0.w;
        y[4]=x1.x+a1.x; y[5]=x1.y+a1.y; y[6]=x1.z+a1.z; y[7]=x1.w+a1.w;
        y[8]=x2.x+a2.x; y[9]=x2.y+a2.y; y[10]=x2.z+a2.z; y[11]=x2.w+a2.w;
        y[12]=x3.x+a3.x; y[13]=x3.y+a3.y; y[14]=x3.z+a3.z; y[15]=x3.w+a3.w;
        float s = 0.0f, sq = 0.0f;
#pragma unroll
        for (int e = 0; e < 16; e++) { s += y[e]; sq += y[e] * y[e]; }
        __syncthreads();
        r2[tid] = make_float2(s, sq);
        __syncthreads();
        for (int st = 32; st; st >>= 1) {
            if (tid < st) {
                r2[tid].x += r2[tid + st].x;
                r2[tid].y += r2[tid + st].y;
            }
            __syncthreads();
        }
        const float mean = r2[0].x * (1.0f / (float)D_IN);
        const float var  = r2[0].y * (1.0f / (float)D_IN) - mean * mean;
        const float rstd = rsqrtf(var + 1e-5f);
        size_t base = (size_t)r * D_IN + d;
#pragma unroll
        for (int e = 0; e < 16; e++) {
            float o = (y[e] - mean) * rstd;
            split_bf16(o, g_hh[base + e], g_hl[base + e]);
        }
    }
}

// ---------------- final residual + LayerNorm: out = LN(sa + tmp) ------------
__global__ __launch_bounds__(256)
void ln_final(float* __restrict__ ext_out)
{
    const int r   = blockIdx.x;
    const int tid = threadIdx.x;

    const float4 av = *(const float4*)(g_sa  + (size_t)r * D_V + tid * 4);
    const float4 bv = *(const float4*)(g_tmp + (size_t)r * D_V + tid * 4);
    float4 y = make_float4(av.x + bv.x, av.y + bv.y, av.z + bv.z, av.w + bv.w);

    float s  = y.x + y.y + y.z + y.w;
    float sq = y.x * y.x + y.y * y.y + y.z * y.z + y.w * y.w;

    __shared__ float2 red2[256];
    red2[tid] = make_float2(s, sq);
    __syncthreads();
    for (int st = 128; st > 0; st >>= 1) {
        if (tid < st) {
            red2[tid].x += red2[tid + st].x;
            red2[tid].y += red2[tid + st].y;
        }
        __syncthreads();
    }
    const float mean = red2[0].x * (1.0f / (float)D_V);
    const float var  = red2[0].y * (1.0f / (float)D_V) - mean * mean;
    const float rstd = rsqrtf(var + 1e-5f);

    *(float4*)(ext_out + (size_t)r * D_V + tid * 4) =
        make_float4((y.x - mean) * rstd, (y.y - mean) * rstd,
                    (y.z - mean) * rstd, (y.w - mean) * rstd);
}

// ---------------- launch sequence ----------------
extern "C" void kernel_launch(void* const* d_in, const int* in_sizes, int n_in,
                              void* d_out, int out_size)
{
    const float* x  = (const float*)d_in[0];
    const float* Wq = (const float*)d_in[1];
    const float* Wk = (const float*)d_in[2];
    const float* Wv = (const float*)d_in[3];
    const float* Wl = (const float*)d_in[4];
    float* out = (float*)d_out;

    const int SMEM_X3 = 2 * (2 * 64 * 128 + 2 * TILE_B);   // 98304
    const int SMEM_X1 = 2 * (128 * 128 + TILE_B);          // 65536
    cudaFuncSetAttribute(gemm_mma<0>, cudaFuncAttributeMaxDynamicSharedMemorySize, SMEM_X3);
    cudaFuncSetAttribute(gemm_mma<1>, cudaFuncAttributeMaxDynamicSharedMemorySize, SMEM_X1);
    cudaFuncSetAttribute(gemm_mma<2>, cudaFuncAttributeMaxDynamicSharedMemorySize, SMEM_X3);

    prep_all<<<512, 256>>>(x, Wq, Wk, Wv, Wl);

    gemm_mma<0><<<2 * NSM, 128, SMEM_X3>>>();   // qkv (bf16x3, 2 CTAs/SM)
    gemm_mma<1><<<NSM, 256, SMEM_X1>>>();       // int8 scores (bf16x1) + row max

    cand_softmax<<<N_TOK, 256>>>();             // fused scan + exact softmax
    attn_av_ln<<<N_TOK, 64>>>(x);               // sparse AV + fused LN1

    gemm_mma<2><<<2 * NSM, 128, SMEM_X3>>>();   // output projection (bf16x3, 2 CTAs/SM)

    ln_final<<<N_TOK, 256>>>(out);
}